// round 3
// baseline (speedup 1.0000x reference)
#include <cuda_runtime.h>
#include <cuda_bf16.h>
#include <cstdint>

#define NROI 128
#define C_CH 512
#define FH 38
#define FW 50
#define K1 25088      // 512*7*7
#define DH 4096
#define SP1 14        // split-K GEMM1: 25088/14 = 1792
#define SP2 8         // split-K GEMM2: 4096/8 = 512
#define SP3 32        // split-K GEMM3: 4096/32 = 128

// ---------------- static scratch (no allocations) ----------------
__device__ float g_x[NROI * K1];
__device__ float g_h1[NROI * DH];
__device__ float g_h2[NROI * DH];
__device__ float g_acc1[SP1 * NROI * DH];
__device__ float g_acc2[SP2 * NROI * DH];
__device__ float g_acc3[SP3 * NROI * 128];
__device__ float g_Wc[DH * 128];   // packed [W_loc | W_score | zeros]

// ---------------- ROI adaptive max pool ----------------
__global__ void pool_kernel(const float* __restrict__ feats,
                            const float* __restrict__ rois) {
    int roi = blockIdx.x;
    float r0 = rois[roi * 4 + 0] * 0.0625f;
    float r1 = rois[roi * 4 + 1] * 0.0625f;
    float r2 = rois[roi * 4 + 2] * 0.0625f;
    float r3 = rois[roi * 4 + 3] * 0.0625f;
    int y0 = (int)truncf(r0), x0 = (int)truncf(r1);
    int y2 = (int)ceilf(r2),  x3 = (int)ceilf(r3);
    int Ly = y2 - y0, Lx = x3 - x0;
    float* xout = g_x + (size_t)roi * K1;
    int base_c = blockIdx.y * 128;
    for (int idx = threadIdx.x; idx < 128 * 49; idx += blockDim.x) {
        int cc = idx / 49, b = idx - cc * 49;
        int c = base_c + cc;
        int i = b / 7, j = b - i * 7;
        int rb0 = y0 + (i * Ly) / 7;
        int rb1 = y0 + ((i + 1) * Ly + 6) / 7;
        int cb0 = x0 + (j * Lx) / 7;
        int cb1 = x0 + ((j + 1) * Lx + 6) / 7;
        const float* f = feats + (size_t)c * (FH * FW);
        float m = -1e30f;
        for (int y = rb0; y < rb1; ++y)
            for (int x = cb0; x < cb1; ++x)
                m = fmaxf(m, __ldg(f + y * FW + x));
        xout[(size_t)c * 49 + b] = m;
    }
}

// ---------------- bf16x3 GEMM helpers ----------------
__device__ __forceinline__ void cvt_pair(float a, float b, uint32_t& hi, uint32_t& lo) {
    __nv_bfloat16 ha = __float2bfloat16(a), hb = __float2bfloat16(b);
    float ra = a - __bfloat162float(ha);
    float rb = b - __bfloat162float(hb);
    __nv_bfloat162 H; H.x = ha; H.y = hb;
    __nv_bfloat162 L; L.x = __float2bfloat16(ra); L.y = __float2bfloat16(rb);
    hi = *reinterpret_cast<uint32_t*>(&H);
    lo = *reinterpret_cast<uint32_t*>(&L);
}
__device__ __forceinline__ void ldsm4(uint32_t& r0, uint32_t& r1, uint32_t& r2, uint32_t& r3, uint32_t a) {
    asm volatile("ldmatrix.sync.aligned.m8n8.x4.shared.b16 {%0,%1,%2,%3},[%4];\n"
                 : "=r"(r0), "=r"(r1), "=r"(r2), "=r"(r3) : "r"(a));
}
__device__ __forceinline__ void ldsm4t(uint32_t& r0, uint32_t& r1, uint32_t& r2, uint32_t& r3, uint32_t a) {
    asm volatile("ldmatrix.sync.aligned.m8n8.x4.trans.shared.b16 {%0,%1,%2,%3},[%4];\n"
                 : "=r"(r0), "=r"(r1), "=r"(r2), "=r"(r3) : "r"(a));
}
__device__ __forceinline__ void mma16816(float* c, const uint32_t* a, const uint32_t* b) {
    asm volatile("mma.sync.aligned.m16n8k16.row.col.f32.bf16.bf16.f32 "
                 "{%0,%1,%2,%3},{%4,%5,%6,%7},{%8,%9},{%0,%1,%2,%3};\n"
                 : "+f"(c[0]), "+f"(c[1]), "+f"(c[2]), "+f"(c[3])
                 : "r"(a[0]), "r"(a[1]), "r"(a[2]), "r"(a[3]), "r"(b[0]), "r"(b[1]));
}

// C-slice[128, 128] = A[128, kchunk] * W[kchunk, 128], bf16x3 in fp32 accum.
// blockIdx.x = N tile, blockIdx.y = K split. Writes acc[split][128][ldN].
__global__ void __launch_bounds__(256)
gemm_bf16x3(const float* __restrict__ A, int lda,
            const float* __restrict__ W, int ldw,
            float* __restrict__ acc, int ldN, int kchunk)
{
    __shared__ __nv_bfloat16 sA[2][128 * 40];   // pitch 40 bf16 (80 B)
    __shared__ __nv_bfloat16 sB[2][32 * 136];   // pitch 136 bf16 (272 B)
    const int tid = threadIdx.x, lane = tid & 31, wid = tid >> 5;
    const int wm = wid & 1, wn = wid >> 1;      // warp tile: 64 x 32
    const int n0 = blockIdx.x * 128;
    const int kbase = blockIdx.y * kchunk;
    const int iters = kchunk / 32;

    float c[4][4][4];
    #pragma unroll
    for (int i = 0; i < 4; i++)
        #pragma unroll
        for (int j = 0; j < 4; j++)
            #pragma unroll
            for (int r = 0; r < 4; r++) c[i][j][r] = 0.f;

    const int ar = tid >> 3, ac = (tid & 7) * 4;      // A: 32 rows/pass, 8 float4/row
    const int bk = tid >> 5, bn = (tid & 31) * 4;     // B: 8 k-rows/pass, 32 float4/row

    float4 av[4], wv[4];
    auto gload = [&](int it) {
        const float* Ap = A + (size_t)ar * lda + kbase + it * 32 + ac;
        #pragma unroll
        for (int p = 0; p < 4; p++) av[p] = *(const float4*)(Ap + (size_t)(32 * p) * lda);
        const float* Wp = W + (size_t)(kbase + it * 32 + bk) * ldw + n0 + bn;
        #pragma unroll
        for (int p = 0; p < 4; p++) wv[p] = *(const float4*)(Wp + (size_t)(8 * p) * ldw);
    };
    auto sstore = [&]() {
        #pragma unroll
        for (int p = 0; p < 4; p++) {
            uint32_t h0, l0, h1, l1;
            cvt_pair(av[p].x, av[p].y, h0, l0);
            cvt_pair(av[p].z, av[p].w, h1, l1);
            int m = ar + 32 * p;
            *(uint2*)&sA[0][m * 40 + ac] = make_uint2(h0, h1);
            *(uint2*)&sA[1][m * 40 + ac] = make_uint2(l0, l1);
        }
        #pragma unroll
        for (int p = 0; p < 4; p++) {
            uint32_t h0, l0, h1, l1;
            cvt_pair(wv[p].x, wv[p].y, h0, l0);
            cvt_pair(wv[p].z, wv[p].w, h1, l1);
            int k = bk + 8 * p;
            *(uint2*)&sB[0][k * 136 + bn] = make_uint2(h0, h1);
            *(uint2*)&sB[1][k * 136 + bn] = make_uint2(l0, l1);
        }
    };

    const uint32_t aH = (uint32_t)__cvta_generic_to_shared(&sA[0][0]);
    const uint32_t aL = (uint32_t)__cvta_generic_to_shared(&sA[1][0]);
    const uint32_t bH = (uint32_t)__cvta_generic_to_shared(&sB[0][0]);
    const uint32_t bL = (uint32_t)__cvta_generic_to_shared(&sB[1][0]);

    gload(0);
    for (int it = 0; it < iters; ++it) {
        sstore();
        __syncthreads();
        if (it + 1 < iters) gload(it + 1);
        #pragma unroll
        for (int ks = 0; ks < 32; ks += 16) {
            // B fragments: ldmatrix.x4.trans covers 16k x 16n = 2 n-frags
            uint32_t bhf[4][2], blf[4][2];
            {
                int krow = ks + ((lane >> 3) & 1) * 8 + (lane & 7);
                #pragma unroll
                for (int np = 0; np < 2; np++) {
                    int ncol = wn * 32 + np * 16 + (lane >> 4) * 8;
                    uint32_t off = (uint32_t)(krow * 136 + ncol) * 2;
                    ldsm4t(bhf[2*np][0], bhf[2*np][1], bhf[2*np+1][0], bhf[2*np+1][1], bH + off);
                    ldsm4t(blf[2*np][0], blf[2*np][1], blf[2*np+1][0], blf[2*np+1][1], bL + off);
                }
            }
            #pragma unroll
            for (int mb = 0; mb < 4; mb++) {
                int mrow = wm * 64 + mb * 16 + (lane & 15);
                uint32_t aoff = (uint32_t)(mrow * 40 + ks + (lane >> 4) * 8) * 2;
                uint32_t ah[4], al[4];
                ldsm4(ah[0], ah[1], ah[2], ah[3], aH + aoff);
                ldsm4(al[0], al[1], al[2], al[3], aL + aoff);
                #pragma unroll
                for (int nb = 0; nb < 4; nb++) {
                    mma16816(c[mb][nb], ah, bhf[nb]);   // hi*hi
                    mma16816(c[mb][nb], ah, blf[nb]);   // hi*lo
                    mma16816(c[mb][nb], al, bhf[nb]);   // lo*hi
                }
            }
        }
        __syncthreads();
    }

    float* accp = acc + (size_t)blockIdx.y * 128 * ldN;
    #pragma unroll
    for (int mb = 0; mb < 4; mb++)
        #pragma unroll
        for (int nb = 0; nb < 4; nb++) {
            int row = wm * 64 + mb * 16 + (lane >> 2);
            int col = n0 + wn * 32 + nb * 8 + (lane & 3) * 2;
            *(float2*)&accp[(size_t)row * ldN + col]       = make_float2(c[mb][nb][0], c[mb][nb][1]);
            *(float2*)&accp[(size_t)(row + 8) * ldN + col] = make_float2(c[mb][nb][2], c[mb][nb][3]);
        }
}

// ---------------- split-K reductions ----------------
__global__ void reduce_relu(const float* __restrict__ acc, const float* __restrict__ bias,
                            float* __restrict__ out, int total, int ldN, int nslice) {
    int i = blockIdx.x * blockDim.x + threadIdx.x;
    if (i >= total) return;
    float s = bias[i % ldN];
    for (int sl = 0; sl < nslice; ++sl) s += acc[(size_t)sl * total + i];
    out[i] = fmaxf(s, 0.f);
}

__global__ void reduce_final(const float* __restrict__ acc,
                             const float* __restrict__ b_loc,
                             const float* __restrict__ b_score,
                             float* __restrict__ out) {
    int i = blockIdx.x * blockDim.x + threadIdx.x;
    if (i >= 128 * 105) return;
    int r = i / 105, col = i - r * 105;
    float s = 0.f;
    for (int sl = 0; sl < SP3; ++sl) s += acc[((size_t)sl * 128 + r) * 128 + col];
    if (col < 84) out[r * 84 + col] = s + b_loc[col];
    else          out[128 * 84 + r * 21 + (col - 84)] = s + b_score[col - 84];
}

__global__ void pack_w(const float* __restrict__ Wl, const float* __restrict__ Ws,
                       float* __restrict__ Wc) {
    int i = blockIdx.x * blockDim.x + threadIdx.x;
    if (i >= DH * 128) return;
    int k = i >> 7, c = i & 127;
    float v = 0.f;
    if (c < 84)       v = Wl[k * 84 + c];
    else if (c < 105) v = Ws[k * 21 + (c - 84)];
    Wc[i] = v;
}

// ---------------- launch ----------------
extern "C" void kernel_launch(void* const* d_in, const int* in_sizes, int n_in,
                              void* d_out, int out_size) {
    const float* feats = (const float*)d_in[0];
    const float* rois  = (const float*)d_in[1];
    const float* W1 = (const float*)d_in[2];
    const float* b1 = (const float*)d_in[3];
    const float* W2 = (const float*)d_in[4];
    const float* b2 = (const float*)d_in[5];
    const float* Wl = (const float*)d_in[6];
    const float* bl = (const float*)d_in[7];
    const float* Ws = (const float*)d_in[8];
    const float* bs = (const float*)d_in[9];
    float* out = (float*)d_out;

    float *gx, *gh1, *gh2, *ga1, *ga2, *ga3, *gwc;
    cudaGetSymbolAddress((void**)&gx,  g_x);
    cudaGetSymbolAddress((void**)&gh1, g_h1);
    cudaGetSymbolAddress((void**)&gh2, g_h2);
    cudaGetSymbolAddress((void**)&ga1, g_acc1);
    cudaGetSymbolAddress((void**)&ga2, g_acc2);
    cudaGetSymbolAddress((void**)&ga3, g_acc3);
    cudaGetSymbolAddress((void**)&gwc, g_Wc);

    pack_w<<<(DH * 128 + 255) / 256, 256>>>(Wl, Ws, gwc);
    pool_kernel<<<dim3(NROI, C_CH / 128), 256>>>(feats, rois);

    // GEMM1: [128,25088] @ [25088,4096]
    gemm_bf16x3<<<dim3(DH / 128, SP1), 256>>>(gx, K1, W1, DH, ga1, DH, K1 / SP1);
    reduce_relu<<<(NROI * DH + 255) / 256, 256>>>(ga1, b1, gh1, NROI * DH, DH, SP1);

    // GEMM2: [128,4096] @ [4096,4096]
    gemm_bf16x3<<<dim3(DH / 128, SP2), 256>>>(gh1, DH, W2, DH, ga2, DH, DH / SP2);
    reduce_relu<<<(NROI * DH + 255) / 256, 256>>>(ga2, b2, gh2, NROI * DH, DH, SP2);

    // GEMM3: [128,4096] @ [4096,128packed]
    gemm_bf16x3<<<dim3(1, SP3), 256>>>(gh2, DH, gwc, 128, ga3, 128, DH / SP3);
    reduce_final<<<(128 * 105 + 255) / 256, 256>>>(ga3, bl, bs, out);
}